// round 1
// baseline (speedup 1.0000x reference)
#include <cuda_runtime.h>
#include <math.h>

// ---------------- problem constants ----------------
#define Bc 2
#define Tc 1024
#define Cc 1024
#define Hc 16
#define Dc 64
#define Ec 16
#define Ic 256
#define Nc (Bc*Tc)   // 2048 tokens

// ---------------- scratch (device globals; no cudaMalloc allowed) ----------------
__device__ float g_h  [Nc*Cc];                 // LN output (reused for h2)
__device__ float g_q  [Nc*Cc];
__device__ float g_k  [Nc*Cc];
__device__ float g_v  [Nc*Cc];
__device__ float g_ao [Nc*Cc];
__device__ float g_x1 [Nc*Cc];                 // x after attention residual
__device__ float g_mid[(long long)Ec*Nc*Ic];   // gelu(h2 @ w1[e]), layout [e][n][i]
__device__ float g_eo_scr[(long long)Nc*Ec*Cc];// fallback if out_size is only x
__device__ float g_mask[Nc*Ec];
__device__ float g_colinv[Ec];
__device__ float g_scores_scr[Nc*Ec];
__device__ float g_kpt_scr[Nc];

// ---------------- helpers ----------------
__device__ __forceinline__ float gelu_f(float x) {
    return 0.5f * x * (1.0f + erff(x * 0.70710678118654752440f));
}

// ---------------- SGEMM core: 128x128 tile, BK=8, 8x8 per thread, 256 threads ----
// A: MxK row-major (lda=K), B: KxN row-major (ldb=Np). M%128==0, N%128==0, K%8==0.
__device__ __forceinline__ void sgemm_core(
    const float* __restrict__ A, const float* __restrict__ B,
    int K, int Np, int brow, int bcol, float acc[8][8])
{
    __shared__ float As[8][128];
    __shared__ float Bs[8][128];
    const int tid  = threadIdx.x;
    const int arow = tid >> 1;          // 0..127
    const int acol = (tid & 1) << 2;    // 0 or 4
    const int brl  = tid >> 5;          // 0..7
    const int bcl  = (tid & 31) << 2;   // 0..124
    const int tx = tid & 15, ty = tid >> 4;

    const float* Ap = A + (long long)(brow + arow) * K + acol;
    const float* Bp = B + (long long)brl * Np + bcol + bcl;

    #pragma unroll
    for (int i = 0; i < 8; i++)
        #pragma unroll
        for (int j = 0; j < 8; j++) acc[i][j] = 0.f;

    for (int k0 = 0; k0 < K; k0 += 8) {
        float4 a4 = *(const float4*)Ap;
        As[acol + 0][arow] = a4.x; As[acol + 1][arow] = a4.y;
        As[acol + 2][arow] = a4.z; As[acol + 3][arow] = a4.w;
        *(float4*)&Bs[brl][bcl] = *(const float4*)Bp;
        __syncthreads();
        #pragma unroll
        for (int kk = 0; kk < 8; kk++) {
            float ra[8], rb[8];
            #pragma unroll
            for (int i = 0; i < 8; i++) ra[i] = As[kk][(ty << 3) + i];
            #pragma unroll
            for (int j = 0; j < 8; j++) rb[j] = Bs[kk][(tx << 3) + j];
            #pragma unroll
            for (int i = 0; i < 8; i++)
                #pragma unroll
                for (int j = 0; j < 8; j++)
                    acc[i][j] = fmaf(ra[i], rb[j], acc[i][j]);
        }
        __syncthreads();
        Ap += 8; Bp += (long long)8 * Np;
    }
}

// EPI: 0=plain, 1=+residual, 2=gelu, 3=*mask(row,z)
template<int EPI>
__global__ void __launch_bounds__(256, 2) gemm_k(
    const float* __restrict__ A, const float* __restrict__ B, float* __restrict__ C,
    int M, int Np, int K,
    long long sA, long long sB, long long sC, int ldc,
    const float* __restrict__ res, int ldres, const float* __restrict__ maskp)
{
    const int z = blockIdx.z;
    A += (long long)z * sA; B += (long long)z * sB; C += (long long)z * sC;
    const int brow = blockIdx.y << 7;
    const int bcol = blockIdx.x << 7;
    float acc[8][8];
    sgemm_core(A, B, K, Np, brow, bcol, acc);

    const int tx = threadIdx.x & 15, ty = threadIdx.x >> 4;
    #pragma unroll
    for (int i = 0; i < 8; i++) {
        const int row = brow + (ty << 3) + i;
        float mval = 0.f;
        if (EPI == 3) mval = maskp[((long long)row << 4) + z];
        #pragma unroll
        for (int j = 0; j < 8; j += 4) {
            const int col = bcol + (tx << 3) + j;
            float4 v = make_float4(acc[i][j], acc[i][j+1], acc[i][j+2], acc[i][j+3]);
            if (EPI == 1) {
                float4 rv = *(const float4*)&res[(long long)row * ldres + col];
                v.x += rv.x; v.y += rv.y; v.z += rv.z; v.w += rv.w;
            } else if (EPI == 2) {
                v.x = gelu_f(v.x); v.y = gelu_f(v.y); v.z = gelu_f(v.z); v.w = gelu_f(v.w);
            } else if (EPI == 3) {
                v.x *= mval; v.y *= mval; v.z *= mval; v.w *= mval;
            }
            *(float4*)&C[(long long)row * ldc + col] = v;
        }
    }
}

// fused QKV: grid.z in {0,1,2} selects weight/output pair (shared A)
__global__ void __launch_bounds__(256, 2) gemm_qkv_k(
    const float* __restrict__ A,
    const float* __restrict__ b0, const float* __restrict__ b1, const float* __restrict__ b2,
    float* __restrict__ c0, float* __restrict__ c1, float* __restrict__ c2)
{
    const int z = blockIdx.z;
    const float* B = (z == 0) ? b0 : (z == 1) ? b1 : b2;
    float* C = (z == 0) ? c0 : (z == 1) ? c1 : c2;
    const int brow = blockIdx.y << 7;
    const int bcol = blockIdx.x << 7;
    float acc[8][8];
    sgemm_core(A, B, Cc, Cc, brow, bcol, acc);
    const int tx = threadIdx.x & 15, ty = threadIdx.x >> 4;
    #pragma unroll
    for (int i = 0; i < 8; i++) {
        const int row = brow + (ty << 3) + i;
        #pragma unroll
        for (int j = 0; j < 8; j += 4) {
            const int col = bcol + (tx << 3) + j;
            float4 v = make_float4(acc[i][j], acc[i][j+1], acc[i][j+2], acc[i][j+3]);
            *(float4*)&C[(long long)row * Cc + col] = v;
        }
    }
}

// ---------------- flash attention (causal, fp32) ----------------
// grid (T/64, H, B), 256 threads. Each thread: q-row r = tid/4, d-quarter qd = tid%4.
__global__ void __launch_bounds__(256) attn_k(
    const float* __restrict__ Q, const float* __restrict__ K,
    const float* __restrict__ V, float* __restrict__ O)
{
    extern __shared__ float sm[];
    float* Ks = sm;                  // [64][65]
    float* Vs = sm + 64 * 65;        // [64][65]
    float* Ps = sm + 2 * 64 * 65;    // [64][65]
    const int qt = blockIdx.x, h = blockIdx.y, b = blockIdx.z;
    const int tid = threadIdx.x;
    const int r = tid >> 2;
    const int qd = tid & 3;
    const long long base = ((long long)b * Tc) * Cc + h * Dc;

    // Q row -> registers, pre-scaled by 1/sqrt(D)
    float qreg[64];
    {
        const float* qr = Q + base + (long long)(qt * 64 + r) * Cc;
        #pragma unroll
        for (int i = 0; i < 64; i += 4) {
            float4 v4 = *(const float4*)(qr + i);
            qreg[i]   = v4.x * 0.125f; qreg[i+1] = v4.y * 0.125f;
            qreg[i+2] = v4.z * 0.125f; qreg[i+3] = v4.w * 0.125f;
        }
    }
    float acc[16];
    #pragma unroll
    for (int i = 0; i < 16; i++) acc[i] = 0.f;
    float mi = -1e30f, li = 0.f;

    for (int kt = 0; kt <= qt; kt++) {
        for (int i = tid; i < 1024; i += 256) {
            const int rr = i >> 4, c4 = (i & 15) << 2;
            const long long goff = base + (long long)(kt * 64 + rr) * Cc + c4;
            float4 kv = *(const float4*)(K + goff);
            float4 vv = *(const float4*)(V + goff);
            float* kd = &Ks[rr * 65 + c4];
            kd[0] = kv.x; kd[1] = kv.y; kd[2] = kv.z; kd[3] = kv.w;
            float* vd = &Vs[rr * 65 + c4];
            vd[0] = vv.x; vd[1] = vv.y; vd[2] = vv.z; vd[3] = vv.w;
        }
        __syncthreads();

        float s[16];
        float mloc = -1e30f;
        const bool diag = (kt == qt);
        #pragma unroll
        for (int jj = 0; jj < 16; jj++) {
            const int j = (jj << 2) + qd;
            const float* kr = &Ks[j * 65];
            float a = 0.f;
            #pragma unroll
            for (int d = 0; d < 64; d++) a = fmaf(qreg[d], kr[d], a);
            if (diag && j > r) a = -1e30f;
            s[jj] = a;
            mloc = fmaxf(mloc, a);
        }
        mloc = fmaxf(mloc, __shfl_xor_sync(0xffffffffu, mloc, 1));
        mloc = fmaxf(mloc, __shfl_xor_sync(0xffffffffu, mloc, 2));
        const float mnew = fmaxf(mi, mloc);
        const float alpha = __expf(mi - mnew);
        float ps = 0.f;
        #pragma unroll
        for (int jj = 0; jj < 16; jj++) {
            const float p = __expf(s[jj] - mnew);
            s[jj] = p; ps += p;
        }
        ps += __shfl_xor_sync(0xffffffffu, ps, 1);
        ps += __shfl_xor_sync(0xffffffffu, ps, 2);
        li = li * alpha + ps;
        mi = mnew;
        #pragma unroll
        for (int dd = 0; dd < 16; dd++) acc[dd] *= alpha;
        #pragma unroll
        for (int jj = 0; jj < 16; jj++) Ps[r * 65 + (jj << 2) + qd] = s[jj];
        __syncthreads();

        const int vo = qd << 4;
        for (int j = 0; j < 64; j++) {
            const float p = Ps[r * 65 + j];
            const float* vr = &Vs[j * 65 + vo];
            #pragma unroll
            for (int dd = 0; dd < 16; dd++) acc[dd] = fmaf(p, vr[dd], acc[dd]);
        }
        __syncthreads();
    }

    const float inv = 1.f / li;
    float* op = O + base + (long long)(qt * 64 + r) * Cc + (qd << 4);
    #pragma unroll
    for (int dd = 0; dd < 16; dd += 4) {
        float4 v = make_float4(acc[dd]*inv, acc[dd+1]*inv, acc[dd+2]*inv, acc[dd+3]*inv);
        *(float4*)(op + dd) = v;
    }
}

// ---------------- LayerNorm: one block per row ----------------
__global__ void __launch_bounds__(256) ln_k(
    const float* __restrict__ x, const float* __restrict__ g,
    const float* __restrict__ b, float* __restrict__ o)
{
    const int n = blockIdx.x, tid = threadIdx.x;
    const long long rb = (long long)n << 10;
    const int c = tid << 2;
    float4 v = *(const float4*)&x[rb + c];
    float s  = v.x + v.y + v.z + v.w;
    float ss = v.x*v.x + v.y*v.y + v.z*v.z + v.w*v.w;
    #pragma unroll
    for (int off = 16; off; off >>= 1) {
        s  += __shfl_xor_sync(0xffffffffu, s,  off);
        ss += __shfl_xor_sync(0xffffffffu, ss, off);
    }
    __shared__ float rs[8], rss[8], mv[2];
    const int w = tid >> 5, lane = tid & 31;
    if (!lane) { rs[w] = s; rss[w] = ss; }
    __syncthreads();
    if (tid == 0) {
        float S = 0, SS = 0;
        #pragma unroll
        for (int i = 0; i < 8; i++) { S += rs[i]; SS += rss[i]; }
        const float mean = S * (1.f / 1024.f);
        const float var  = SS * (1.f / 1024.f) - mean * mean;
        mv[0] = mean; mv[1] = rsqrtf(var + 1e-5f);
    }
    __syncthreads();
    const float mean = mv[0], rstd = mv[1];
    float4 gg = *(const float4*)&g[c], bb = *(const float4*)&b[c];
    float4 ov;
    ov.x = (v.x - mean) * rstd * gg.x + bb.x;
    ov.y = (v.y - mean) * rstd * gg.y + bb.y;
    ov.z = (v.z - mean) * rstd * gg.z + bb.z;
    ov.w = (v.w - mean) * rstd * gg.w + bb.w;
    *(float4*)&o[rb + c] = ov;
}

// ---------------- sim column inverse norms ----------------
__global__ void __launch_bounds__(256) colnorm_k(
    const float* __restrict__ sim, float* __restrict__ colinv)
{
    const int e = blockIdx.x, tid = threadIdx.x;
    float s = 0.f;
    for (int cc = tid; cc < 1024; cc += 256) {
        const float v = sim[cc * 16 + e];
        s = fmaf(v, v, s);
    }
    #pragma unroll
    for (int off = 16; off; off >>= 1) s += __shfl_xor_sync(0xffffffffu, s, off);
    __shared__ float rs[8];
    const int w = tid >> 5, lane = tid & 31;
    if (!lane) rs[w] = s;
    __syncthreads();
    if (tid == 0) {
        float S = 0;
        #pragma unroll
        for (int i = 0; i < 8; i++) S += rs[i];
        colinv[e] = rsqrtf(S);
    }
}

// ---------------- routing: scores, mask, k_per_token (one block per token) ----
__global__ void __launch_bounds__(256) score_k(
    const float* __restrict__ h2, const float* __restrict__ sim,
    const float* __restrict__ thr, const float* __restrict__ colinv,
    float* __restrict__ oscores, float* __restrict__ okpt, float* __restrict__ maskb)
{
    const int n = blockIdx.x, tid = threadIdx.x;
    const long long rb = (long long)n << 10;
    const int c = tid << 2;
    float4 v = *(const float4*)&h2[rb + c];
    float ss = v.x*v.x + v.y*v.y + v.z*v.z + v.w*v.w;
    float accd[16];
    #pragma unroll
    for (int e = 0; e < 16; e++) accd[e] = 0.f;
    const float hv[4] = {v.x, v.y, v.z, v.w};
    #pragma unroll
    for (int cc = 0; cc < 4; cc++) {
        const float* sr = &sim[(long long)(c + cc) << 4];
        #pragma unroll
        for (int e = 0; e < 16; e++) accd[e] = fmaf(hv[cc], sr[e], accd[e]);
    }
    #pragma unroll
    for (int off = 16; off; off >>= 1) ss += __shfl_xor_sync(0xffffffffu, ss, off);

    __shared__ float rs[8];
    __shared__ float red[16 * 8];
    __shared__ float smask[16];
    __shared__ float srn;
    const int w = tid >> 5, lane = tid & 31;
    if (!lane) rs[w] = ss;
    #pragma unroll
    for (int e = 0; e < 16; e++) {
        float t = accd[e];
        #pragma unroll
        for (int off = 16; off; off >>= 1) t += __shfl_xor_sync(0xffffffffu, t, off);
        if (!lane) red[e * 8 + w] = t;
    }
    __syncthreads();
    if (tid == 0) {
        float S = 0;
        #pragma unroll
        for (int i = 0; i < 8; i++) S += rs[i];
        srn = rsqrtf(S);
    }
    __syncthreads();
    if (tid < 16) {
        float sum = 0;
        #pragma unroll
        for (int i = 0; i < 8; i++) sum += red[tid * 8 + i];
        const float sc = sum * srn * colinv[tid];
        oscores[(n << 4) + tid] = sc;
        const float m = (sc > thr[0]) ? 1.f : 0.f;
        maskb[(n << 4) + tid] = m;
        smask[tid] = m;
    }
    __syncthreads();
    if (tid == 0) {
        float cnt = 0;
        #pragma unroll
        for (int e = 0; e < 16; e++) cnt += smask[e];
        okpt[n] = cnt;
    }
}

// ---------------- final: x_out = x1 + sum_e mask[e] * eo[n,e,:] ----------------
__global__ void __launch_bounds__(256) final_k(
    const float* __restrict__ x1, const float* __restrict__ eo,
    const float* __restrict__ maskb, float* __restrict__ ox)
{
    const int n = blockIdx.x, tid = threadIdx.x;
    __shared__ float mk[16];
    if (tid < 16) mk[tid] = maskb[(n << 4) + tid];
    __syncthreads();
    const int c = tid << 2;
    const long long rb = (long long)n << 10;
    float4 v = *(const float4*)&x1[rb + c];
    #pragma unroll
    for (int e = 0; e < 16; e++) {
        if (mk[e] != 0.f) {
            const float4 wv = *(const float4*)&eo[(((long long)(n * 16 + e)) << 10) + c];
            v.x += wv.x; v.y += wv.y; v.z += wv.z; v.w += wv.w;
        }
    }
    *(float4*)&ox[rb + c] = v;
}

// ---------------- launcher ----------------
extern "C" void kernel_launch(void* const* d_in, const int* in_sizes, int n_in,
                              void* d_out, int out_size)
{
    (void)in_sizes; (void)n_in;
    const float* x    = (const float*)d_in[0];
    const float* ln1g = (const float*)d_in[1];
    const float* ln1b = (const float*)d_in[2];
    const float* ln2g = (const float*)d_in[3];
    const float* ln2b = (const float*)d_in[4];
    const float* wq   = (const float*)d_in[5];
    const float* wk   = (const float*)d_in[6];
    const float* wv   = (const float*)d_in[7];
    const float* wo   = (const float*)d_in[8];
    const float* sim  = (const float*)d_in[9];
    const float* thr  = (const float*)d_in[10];
    const float* w1   = (const float*)d_in[11];
    const float* w2   = (const float*)d_in[12];

    float *ph, *pq, *pk, *pv, *pao, *px1, *pmid, *peos, *pmask, *pcol, *pssc, *pkpt;
    cudaGetSymbolAddress((void**)&ph,   g_h);
    cudaGetSymbolAddress((void**)&pq,   g_q);
    cudaGetSymbolAddress((void**)&pk,   g_k);
    cudaGetSymbolAddress((void**)&pv,   g_v);
    cudaGetSymbolAddress((void**)&pao,  g_ao);
    cudaGetSymbolAddress((void**)&px1,  g_x1);
    cudaGetSymbolAddress((void**)&pmid, g_mid);
    cudaGetSymbolAddress((void**)&peos, g_eo_scr);
    cudaGetSymbolAddress((void**)&pmask,g_mask);
    cudaGetSymbolAddress((void**)&pcol, g_colinv);
    cudaGetSymbolAddress((void**)&pssc, g_scores_scr);
    cudaGetSymbolAddress((void**)&pkpt, g_kpt_scr);

    const long long XN  = (long long)Nc * Cc;        // 2,097,152
    const long long SCN = (long long)Nc * Ec;        // 32,768
    const long long EON = (long long)Nc * Ec * Cc;   // 33,554,432
    const bool full = ((long long)out_size >= XN + SCN + EON + Nc);

    float* out   = (float*)d_out;
    float* o_x   = out;
    float* o_sc  = full ? out + XN             : pssc;
    float* o_eo  = full ? out + XN + SCN       : peos;
    float* o_kpt = full ? out + XN + SCN + EON : pkpt;

    const int SM_ATTN = 3 * 64 * 65 * 4;  // 49,920 B
    cudaFuncSetAttribute(attn_k, cudaFuncAttributeMaxDynamicSharedMemorySize, SM_ATTN);

    // routing column norms (independent; run early)
    colnorm_k<<<16, 256>>>(sim, pcol);

    // LN1
    ln_k<<<Nc, 256>>>(x, ln1g, ln1b, ph);

    // fused QKV projections (384 blocks in one launch)
    gemm_qkv_k<<<dim3(8, 16, 3), 256>>>(ph, wq, wk, wv, pq, pk, pv);

    // causal flash attention
    attn_k<<<dim3(Tc / 64, Hc, Bc), 256, SM_ATTN>>>(pq, pk, pv, pao);

    // output projection + residual: x1 = hidden + ao @ wo
    gemm_k<1><<<dim3(8, 16, 1), 256>>>(pao, wo, px1, Nc, Cc, Cc,
                                       0, 0, 0, Cc, x, Cc, nullptr);

    // LN2 (h reused as h2)
    ln_k<<<Nc, 256>>>(px1, ln2g, ln2b, ph);

    // routing scores / mask / k_per_token
    score_k<<<Nc, 256>>>(ph, sim, thr, pcol, o_sc, o_kpt, pmask);

    // mid[e] = gelu(h2 @ w1[e])   (batched over e)
    gemm_k<2><<<dim3(2, 16, Ec), 256>>>(ph, w1, pmid, Nc, Ic, Cc,
                                        0, (long long)Cc * Ic, (long long)Nc * Ic,
                                        Ic, nullptr, 0, nullptr);

    // eo[n,e,:] = (mid[e] @ w2[e]) * mask[n,e]   (batched over e; ldc strides into [n][e][c])
    gemm_k<3><<<dim3(8, 16, Ec), 256>>>(pmid, w2, o_eo, Nc, Cc, Ic,
                                        (long long)Nc * Ic, (long long)Ic * Cc,
                                        (long long)Cc, Ec * Cc, nullptr, 0, pmask);

    // x_out = x1 + sum_e eo (masked)
    final_k<<<Nc, 256>>>(px1, o_eo, pmask, o_x);
}